// round 1
// baseline (speedup 1.0000x reference)
#include <cuda_runtime.h>
#include <math.h>

// ---------------------------------------------------------------------------
// AttentionLayer: B=16, T=4096, D=1024, NH=16, HD=64, Tq=1.
// Folded formulation: never materialize K or V.
//   qt[b,h,:] = SCALE * Wk_h^T q[b,h]          (R^1024 per (b,h))
//   scores[b,h,t] = qt[b,h] . enc[b,t]
//   u[b,h,:] = sum_t attn[b,h,t] * enc[b,t,:]
//   ctx[b, h*64+j] = Wv[h*64+j,:] . u[b,h,:]
//   out = (silu(cat(dec_h,ctx) @ W1^T)) @ W2^T
// ---------------------------------------------------------------------------

#define B_   16
#define T_   4096
#define D_   1024
#define NH_  16
#define HD_  64
#define NC_  16          // t-chunks for pass B partials (chunk = 256 rows)
#define TCH_ 256
#define TBLK_ 256        // t-rows per CTA in pass A

// scratch (no cudaMalloc allowed)
__device__ __align__(16) float g_q  [B_*D_];            // q projection
__device__ __align__(16) float g_qt [B_*D_*NH_];        // [b][d][h]  (scaled)
__device__ __align__(16) float g_sc [B_*NH_*T_];        // [b][h][t]
__device__ __align__(16) float g_at [B_*T_*NH_];        // [b][t][h]  normalized attn
__device__ __align__(16) float g_up [NC_*B_*NH_*D_];    // chunk partials of u
__device__ __align__(16) float g_u  [B_*NH_*D_];        // [b][h][d]
__device__ __align__(16) float g_ctx[B_*D_];
__device__ __align__(16) float g_hb [B_*4*D_];

// ---- packed f32x2 helpers (Blackwell) -------------------------------------
__device__ __forceinline__ void fma2(unsigned long long &acc,
                                     unsigned long long a,
                                     unsigned long long b) {
    asm("fma.rn.f32x2 %0, %1, %2, %0;" : "+l"(acc) : "l"(a), "l"(b));
}
__device__ __forceinline__ unsigned long long pack2(float v) {
    unsigned long long r;
    asm("mov.b64 %0, {%1, %1};" : "=l"(r) : "f"(v));
    return r;
}
__device__ __forceinline__ float2 unpack2(unsigned long long v) {
    float2 r;
    asm("mov.b64 {%0, %1}, %2;" : "=f"(r.x), "=f"(r.y) : "l"(v));
    return r;
}
__device__ __forceinline__ float wred(float s) {
    #pragma unroll
    for (int o = 16; o > 0; o >>= 1) s += __shfl_xor_sync(0xffffffffu, s, o);
    return s;
}

// ---------------------------------------------------------------------------
// K1: q[b,o] = dec_h[b,:] . Wq[o,:]     (warp per output)
__global__ void k_qproj(const float* __restrict__ dec_h,
                        const float* __restrict__ Wq) {
    int out  = blockIdx.x * 8 + (threadIdx.x >> 5);
    int lane = threadIdx.x & 31;
    int b = out >> 10, o = out & 1023;
    const float4* w4 = (const float4*)(Wq + (size_t)o * D_);
    const float4* x4 = (const float4*)(dec_h + (size_t)b * D_);
    float s = 0.f;
    #pragma unroll
    for (int i = lane; i < 256; i += 32) {
        float4 w = w4[i], x = x4[i];
        s += w.x * x.x + w.y * x.y + w.z * x.z + w.w * x.w;
    }
    s = wred(s);
    if (lane == 0) g_q[out] = s;
}

// ---------------------------------------------------------------------------
// K2: qt[b][d][h] = SCALE * sum_j q[b, h*64+j] * Wk[h*64+j, d]
// grid = NH (one block per head, reads Wk rows once), 256 threads, 4 d each.
__global__ void k_qtilde(const float* __restrict__ Wk) {
    int h = blockIdx.x, tid = threadIdx.x;
    __shared__ float qs[B_ * HD_];           // q[b][j] for this head
    for (int i = tid; i < B_ * HD_; i += 256) {
        int b = i >> 6, j = i & 63;
        qs[i] = g_q[b * D_ + h * HD_ + j];
    }
    __syncthreads();
    float acc[4][B_];
    #pragma unroll
    for (int dk = 0; dk < 4; dk++)
        #pragma unroll
        for (int b = 0; b < B_; b++) acc[dk][b] = 0.f;
    for (int j = 0; j < HD_; j++) {
        const float* wrow = Wk + (size_t)(h * HD_ + j) * D_;
        float w0 = wrow[tid], w1 = wrow[tid + 256],
              w2 = wrow[tid + 512], w3 = wrow[tid + 768];
        #pragma unroll
        for (int b = 0; b < B_; b++) {
            float qv = qs[b * HD_ + j];
            acc[0][b] += w0 * qv; acc[1][b] += w1 * qv;
            acc[2][b] += w2 * qv; acc[3][b] += w3 * qv;
        }
    }
    const float scale = 0.125f;  // 1/sqrt(64)
    #pragma unroll
    for (int dk = 0; dk < 4; dk++) {
        int d = tid + dk * 256;
        #pragma unroll
        for (int b = 0; b < B_; b++)
            g_qt[(size_t)b * D_ * NH_ + d * NH_ + h] = scale * acc[dk][b];
    }
}

// ---------------------------------------------------------------------------
// K3 (pass A): scores[b][h][t] = qt[b,:,h] . enc[b,t,:]
// Block (b, tb): 256 threads; each thread owns one t-row, all 16 heads in regs.
__global__ void k_scores(const float* __restrict__ enc) {
    int b  = blockIdx.x;
    int t0 = blockIdx.y * TBLK_;
    int tid = threadIdx.x;
    __shared__ __align__(16) float enc_s[TBLK_ * 17];   // pitch 17 -> no conflicts
    __shared__ __align__(16) float qt_s[16 * NH_];
    const float* encb = enc + ((size_t)b * T_ + t0) * D_;
    const float* qtb  = g_qt + (size_t)b * D_ * NH_;

    unsigned long long acc[8];
    #pragma unroll
    for (int k = 0; k < 8; k++) acc[k] = 0ull;

    for (int dc = 0; dc < D_; dc += 16) {
        #pragma unroll
        for (int k = 0; k < 16; k++) {
            int idx = (k << 8) + tid;
            int r = idx >> 4, c = idx & 15;
            enc_s[r * 17 + c] = encb[(size_t)r * D_ + dc + c];
        }
        qt_s[tid] = qtb[dc * NH_ + tid];
        __syncthreads();
        #pragma unroll
        for (int d = 0; d < 16; d++) {
            unsigned long long e2 = pack2(enc_s[tid * 17 + d]);
            const ulonglong2* qp = (const ulonglong2*)(qt_s + (d << 4));
            ulonglong2 q0 = qp[0], q1 = qp[1], q2 = qp[2], q3 = qp[3];
            fma2(acc[0], e2, q0.x); fma2(acc[1], e2, q0.y);
            fma2(acc[2], e2, q1.x); fma2(acc[3], e2, q1.y);
            fma2(acc[4], e2, q2.x); fma2(acc[5], e2, q2.y);
            fma2(acc[6], e2, q3.x); fma2(acc[7], e2, q3.y);
        }
        __syncthreads();
    }
    int t = t0 + tid;
    #pragma unroll
    for (int k = 0; k < 8; k++) {
        float2 v = unpack2(acc[k]);
        g_sc[((size_t)b * NH_ + 2 * k    ) * T_ + t] = v.x;
        g_sc[((size_t)b * NH_ + 2 * k + 1) * T_ + t] = v.y;
    }
}

// ---------------------------------------------------------------------------
// K4: softmax over t per (b,h); writes normalized attn as [b][t][h]
__global__ void k_softmax() {
    int bh = blockIdx.x;                 // 256 blocks
    int b = bh >> 4, h = bh & 15;
    const float* sc = g_sc + (size_t)bh * T_;
    float* at = g_at + (size_t)b * T_ * NH_ + h;
    int tid = threadIdx.x;               // 256
    __shared__ float red[8];
    __shared__ float sbc;

    float v[16];
    float m = -1e30f;
    #pragma unroll
    for (int k = 0; k < 16; k++) { v[k] = sc[tid + (k << 8)]; m = fmaxf(m, v[k]); }
    #pragma unroll
    for (int o = 16; o > 0; o >>= 1) m = fmaxf(m, __shfl_xor_sync(0xffffffffu, m, o));
    if ((tid & 31) == 0) red[tid >> 5] = m;
    __syncthreads();
    if (tid == 0) {
        float mm = red[0];
        #pragma unroll
        for (int i = 1; i < 8; i++) mm = fmaxf(mm, red[i]);
        sbc = mm;
    }
    __syncthreads();
    m = sbc;
    float s = 0.f;
    #pragma unroll
    for (int k = 0; k < 16; k++) { v[k] = expf(v[k] - m); s += v[k]; }
    s = wred(s);
    __syncthreads();
    if ((tid & 31) == 0) red[tid >> 5] = s;
    __syncthreads();
    if (tid == 0) {
        float ss = 0.f;
        #pragma unroll
        for (int i = 0; i < 8; i++) ss += red[i];
        sbc = 1.f / ss;
    }
    __syncthreads();
    float inv = sbc;
    #pragma unroll
    for (int k = 0; k < 16; k++) at[(size_t)(tid + (k << 8)) * NH_] = v[k] * inv;
}

// ---------------------------------------------------------------------------
// K5 (pass B): u_part[c][b][h][d] = sum_{t in chunk} attn[b,t,h] * enc[b,t,d]
// Block (b, c): 256 threads; thread owns d = 4*tid..4*tid+3, all 16 heads.
__global__ void k_wsum(const float* __restrict__ enc) {
    int b = blockIdx.x, c = blockIdx.y;
    int tid = threadIdx.x;
    __shared__ __align__(16) float w_s[TCH_ * NH_];     // 16 KB
    #pragma unroll
    for (int k = 0; k < 16; k++) {
        int idx = (k << 8) + tid;
        w_s[idx] = g_at[((size_t)b * T_ + c * TCH_) * NH_ + idx];
    }
    __syncthreads();

    unsigned long long u[4][8];
    #pragma unroll
    for (int d = 0; d < 4; d++)
        #pragma unroll
        for (int hp = 0; hp < 8; hp++) u[d][hp] = 0ull;

    const float4* e4 = (const float4*)(enc + ((size_t)b * T_ + (size_t)c * TCH_) * D_) + tid;
    #pragma unroll 4
    for (int t = 0; t < TCH_; t++) {
        float4 ev = e4[(size_t)t * (D_ / 4)];
        const ulonglong2* wp = (const ulonglong2*)(w_s + t * NH_);
        ulonglong2 w0 = wp[0], w1 = wp[1], w2 = wp[2], w3 = wp[3];
        unsigned long long e0 = pack2(ev.x), e1 = pack2(ev.y),
                           e2 = pack2(ev.z), e3 = pack2(ev.w);
        fma2(u[0][0], e0, w0.x); fma2(u[0][1], e0, w0.y);
        fma2(u[0][2], e0, w1.x); fma2(u[0][3], e0, w1.y);
        fma2(u[0][4], e0, w2.x); fma2(u[0][5], e0, w2.y);
        fma2(u[0][6], e0, w3.x); fma2(u[0][7], e0, w3.y);
        fma2(u[1][0], e1, w0.x); fma2(u[1][1], e1, w0.y);
        fma2(u[1][2], e1, w1.x); fma2(u[1][3], e1, w1.y);
        fma2(u[1][4], e1, w2.x); fma2(u[1][5], e1, w2.y);
        fma2(u[1][6], e1, w3.x); fma2(u[1][7], e1, w3.y);
        fma2(u[2][0], e2, w0.x); fma2(u[2][1], e2, w0.y);
        fma2(u[2][2], e2, w1.x); fma2(u[2][3], e2, w1.y);
        fma2(u[2][4], e2, w2.x); fma2(u[2][5], e2, w2.y);
        fma2(u[2][6], e2, w3.x); fma2(u[2][7], e2, w3.y);
        fma2(u[3][0], e3, w0.x); fma2(u[3][1], e3, w0.y);
        fma2(u[3][2], e3, w1.x); fma2(u[3][3], e3, w1.y);
        fma2(u[3][4], e3, w2.x); fma2(u[3][5], e3, w2.y);
        fma2(u[3][6], e3, w3.x); fma2(u[3][7], e3, w3.y);
    }
    // write: g_up[((c*B + b)*NH + h)*D + 4*tid + d]
    #pragma unroll
    for (int hp = 0; hp < 8; hp++) {
        float2 a0 = unpack2(u[0][hp]), a1 = unpack2(u[1][hp]),
               a2 = unpack2(u[2][hp]), a3 = unpack2(u[3][hp]);
        float4 lo = make_float4(a0.x, a1.x, a2.x, a3.x);
        float4 hi = make_float4(a0.y, a1.y, a2.y, a3.y);
        size_t base = (((size_t)c * B_ + b) * NH_) * D_ + 4 * tid;
        *(float4*)(g_up + base + (size_t)(2 * hp)     * D_) = lo;
        *(float4*)(g_up + base + (size_t)(2 * hp + 1) * D_) = hi;
    }
}

// ---------------------------------------------------------------------------
// K6: u[b][h][d] = sum_c u_part[c][b][h][d]
__global__ void k_combine() {
    int idx = blockIdx.x * 256 + threadIdx.x;   // B*NH*D = 262144
    float s = 0.f;
    #pragma unroll
    for (int c = 0; c < NC_; c++) s += g_up[(size_t)c * (B_ * NH_ * D_) + idx];
    g_u[idx] = s;
}

// ---------------------------------------------------------------------------
// K7: ctx[b, o] = Wv[o,:] . u[b, o>>6, :]   (warp per output)
__global__ void k_ctx(const float* __restrict__ Wv) {
    int out  = blockIdx.x * 8 + (threadIdx.x >> 5);
    int lane = threadIdx.x & 31;
    int b = out >> 10, o = out & 1023, h = o >> 6;
    const float4* w4 = (const float4*)(Wv + (size_t)o * D_);
    const float4* u4 = (const float4*)(g_u + ((size_t)b * NH_ + h) * D_);
    float s = 0.f;
    #pragma unroll
    for (int i = lane; i < 256; i += 32) {
        float4 w = w4[i], x = u4[i];
        s += w.x * x.x + w.y * x.y + w.z * x.z + w.w * x.w;
    }
    s = wred(s);
    if (lane == 0) g_ctx[out] = s;
}

// ---------------------------------------------------------------------------
// K8: h[b,j] = silu( W1[j,0:1024].dec_h[b] + W1[j,1024:2048].ctx[b] )
__global__ void k_ffn1(const float* __restrict__ dec_h,
                       const float* __restrict__ W1) {
    int out  = blockIdx.x * 8 + (threadIdx.x >> 5);   // B*4096 = 65536
    int lane = threadIdx.x & 31;
    int b = out >> 12, j = out & 4095;
    const float4* w4 = (const float4*)(W1 + (size_t)j * (2 * D_));
    const float4* xa = (const float4*)(dec_h + (size_t)b * D_);
    const float4* xb = (const float4*)(g_ctx + (size_t)b * D_);
    float s = 0.f;
    #pragma unroll
    for (int i = lane; i < 256; i += 32) {
        float4 w = w4[i], x = xa[i];
        s += w.x * x.x + w.y * x.y + w.z * x.z + w.w * x.w;
    }
    #pragma unroll
    for (int i = lane; i < 256; i += 32) {
        float4 w = w4[256 + i], x = xb[i];
        s += w.x * x.x + w.y * x.y + w.z * x.z + w.w * x.w;
    }
    s = wred(s);
    if (lane == 0) g_hb[out] = s / (1.f + expf(-s));   // silu
}

// ---------------------------------------------------------------------------
// K9: out[b,o] = W2[o,:] . h[b,:]
__global__ void k_ffn2(const float* __restrict__ W2, float* __restrict__ outp) {
    int out  = blockIdx.x * 8 + (threadIdx.x >> 5);   // 16384
    int lane = threadIdx.x & 31;
    int b = out >> 10, o = out & 1023;
    const float4* w4 = (const float4*)(W2 + (size_t)o * (4 * D_));
    const float4* h4 = (const float4*)(g_hb + (size_t)b * (4 * D_));
    float s = 0.f;
    #pragma unroll
    for (int i = lane; i < 1024; i += 32) {
        float4 w = w4[i], x = h4[i];
        s += w.x * x.x + w.y * x.y + w.z * x.z + w.w * x.w;
    }
    s = wred(s);
    if (lane == 0) outp[out] = s;
}

// ---------------------------------------------------------------------------
extern "C" void kernel_launch(void* const* d_in, const int* in_sizes, int n_in,
                              void* d_out, int out_size) {
    const float* dec_h = (const float*)d_in[0];
    const float* enc   = (const float*)d_in[1];
    const float* Wq    = (const float*)d_in[2];
    const float* Wk    = (const float*)d_in[3];
    const float* Wv    = (const float*)d_in[4];
    const float* W1    = (const float*)d_in[5];
    const float* W2    = (const float*)d_in[6];
    float* outp = (float*)d_out;

    k_qproj  <<<2048, 256>>>(dec_h, Wq);
    k_qtilde <<<NH_,  256>>>(Wk);
    k_scores <<<dim3(B_, T_ / TBLK_), 256>>>(enc);
    k_softmax<<<B_ * NH_, 256>>>();
    k_wsum   <<<dim3(B_, NC_), 256>>>(enc);
    k_combine<<<(B_ * NH_ * D_) / 256, 256>>>();
    k_ctx    <<<2048, 256>>>(Wv);
    k_ffn1   <<<8192, 256>>>(dec_h, W1);
    k_ffn2   <<<2048, 256>>>(W2, outp);
}